// round 15
// baseline (speedup 1.0000x reference)
#include <cuda_runtime.h>

#define NUM_R 725
#define NUM_T 180
#define IMG_N 512
#define NSPLIT 8                 // n-dimension split (92x8=736 blocks ~ 1 wave @5/SM)
#define TB 256                   // threads per block
#define NROWS (IMG_N / NSPLIT)   // 64 sweep rows per block
#define CHUNK 8                  // rows per pipeline stage
#define XSTRIDE 516              // x-class: 512 data + 4 pad (16B-aligned rows)
#define XBUF (CHUNK * XSTRIDE)   // 4128 words per x buffer
#define YSTRIDE 10               // y-class: 8 data + 2 pad words per x (8B-aligned)
#define YBUF (513 * YSTRIDE)     // 5130 words per y buffer (x=512 row = zeros)
#define NCHUNK (NROWS / CHUNK)   // 8 stages
#define NPAIR 92                 // theta pair-slots (88 pairs + 4 solos)

// Scratch (device global per the allocation-free rule)
__device__ float g_scratch[NSPLIT * NUM_T * NUM_R];     // partials [sp][t][r]

typedef unsigned long long ull;

// ---- packed f32x2 helpers (Blackwell) --------------------------------------
__device__ __forceinline__ ull pk2(float lo, float hi) {
    ull r; asm("mov.b64 %0, {%1, %2};" : "=l"(r) : "f"(lo), "f"(hi)); return r;
}
__device__ __forceinline__ void upk2(float& lo, float& hi, ull v) {
    asm("mov.b64 {%0, %1}, %2;" : "=f"(lo), "=f"(hi) : "l"(v));
}
__device__ __forceinline__ ull mul2(ull a, ull b) {
    ull d; asm("mul.rn.f32x2 %0, %1, %2;" : "=l"(d) : "l"(a), "l"(b)); return d;
}
__device__ __forceinline__ ull add2(ull a, ull b) {
    ull d; asm("add.rn.f32x2 %0, %1, %2;" : "=l"(d) : "l"(a), "l"(b)); return d;
}
__device__ __forceinline__ ull fma2(ull a, ull b, ull c) {
    ull d; asm("fma.rn.f32x2 %0, %1, %2, %3;" : "=l"(d) : "l"(a), "l"(b), "l"(c)); return d;
}

// ---- cp.async helpers ------------------------------------------------------
__device__ __forceinline__ void cpasync16(void* smem, const void* gmem) {
    unsigned sa = (unsigned)__cvta_generic_to_shared(smem);
    asm volatile("cp.async.cg.shared.global [%0], [%1], 16;" :: "r"(sa), "l"(gmem));
}
__device__ __forceinline__ void cpasync8(void* smem, const void* gmem) {
    unsigned sa = (unsigned)__cvta_generic_to_shared(smem);
    asm volatile("cp.async.ca.shared.global [%0], [%1], 8;" :: "r"(sa), "l"(gmem));
}
__device__ __forceinline__ void cpasync_commit() {
    asm volatile("cp.async.commit_group;");
}
template <int N>
__device__ __forceinline__ void cpasync_wait() {
    asm volatile("cp.async.wait_group %0;" :: "n"(N));
}

// ---------------------------------------------------------------------------
// Per-chunk compute body (shared by both classes).
// JS = word stride between j-rows; US = word stride between u-samples.
//   x-class: JS=XSTRIDE, US=1   (buf[j*516 + u])
//   y-class: JS=1,       US=10  (buf[u*10  + j])
// OOB u -> min(u,512) lands on a zeroed pad slot in both layouts.
// ---------------------------------------------------------------------------
template <int JS, int US>
__device__ __forceinline__ void chunk_body(
    const float* __restrict__ bcur, float n0f, ull rho01, float rho2,
    ull ncoef2A, ull rden2A, ull nden2A, float rdenA, float ndenA,
    ull ncoef2B, ull rden2B, ull nden2B, float rdenB, float ndenB,
    float& a0A, float& a1A, float& a2A,
    float& a0B, float& a1B, float& a2B)
{
    const ull ones2 = pk2(1.0f, 1.0f);
    ull nf2 = pk2(n0f, n0f);
#pragma unroll 2
    for (int j = 0; j < CHUNK; j++) {
        const float* __restrict__ row = bcur + j * JS;

        // ---------- theta A: packed (rho0,rho1) + scalar rho2 --------------
        ull nnc2A = mul2(nf2, ncoef2A);
        float nnlA, nnhA; upk2(nnlA, nnhA, nnc2A);     // lo = n*(-coefA)
        ull num2A = add2(rho01, nnc2A);
        ull q02A  = mul2(num2A, rden2A);
        ull e2A   = fma2(nden2A, q02A, num2A);
        ull q2A   = fma2(e2A, rden2A, q02A);           // RN(num/den)
        float qaA, qbA; upk2(qaA, qbA, q2A);
        float numsA = __fadd_rn(rho2, nnlA);
        float q0sA  = __fmul_rn(numsA, rdenA);
        float qsA   = __fmaf_rn(__fmaf_rn(ndenA, q0sA, numsA), rdenA, q0sA);

        // ---------- theta B -------------------------------------------------
        ull nnc2B = mul2(nf2, ncoef2B);
        float nnlB, nnhB; upk2(nnlB, nnhB, nnc2B);
        ull num2B = add2(rho01, nnc2B);
        ull q02B  = mul2(num2B, rden2B);
        ull e2B   = fma2(nden2B, q02B, num2B);
        ull q2B   = fma2(e2B, rden2B, q02B);
        float qaB, qbB; upk2(qaB, qbB, q2B);
        float numsB = __fadd_rn(rho2, nnlB);
        float q0sB  = __fmul_rn(numsB, rdenB);
        float qsB   = __fmaf_rn(__fmaf_rn(ndenB, q0sB, numsB), rdenB, q0sB);

        // ---------- gathers (zero-pad OOB) ----------------------------------
        unsigned u0A = min((unsigned)__float2int_rn(qaA), (unsigned)IMG_N);
        unsigned u1A = min((unsigned)__float2int_rn(qbA), (unsigned)IMG_N);
        unsigned u2A = min((unsigned)__float2int_rn(qsA), (unsigned)IMG_N);
        unsigned u0B = min((unsigned)__float2int_rn(qaB), (unsigned)IMG_N);
        unsigned u1B = min((unsigned)__float2int_rn(qbB), (unsigned)IMG_N);
        unsigned u2B = min((unsigned)__float2int_rn(qsB), (unsigned)IMG_N);
        a0A = __fadd_rn(a0A, row[u0A * US]);
        a1A = __fadd_rn(a1A, row[u1A * US]);
        a2A = __fadd_rn(a2A, row[u2A * US]);
        a0B = __fadd_rn(a0B, row[u0B * US]);
        a1B = __fadd_rn(a1B, row[u1B * US]);
        a2B = __fadd_rn(a2B, row[u2B * US]);

        nf2 = add2(nf2, ones2);
    }
}

// ---------------------------------------------------------------------------
// Main Hough kernel, theta-paired, self-staging (NO transpose kernel).
// blockIdx.x = pair slot, blockIdx.y = n-split. Two adjacent same-class
// thetas per block from one staged chunk stream. Warp w owns rhos
// [96w, 96w+96); lane l handles r = 96w + 32k + l (k=0..2). Union 8-corner
// band test per chunk skips dead tiles (all samples OOB -> +0.0f).
// x-class blocks stage img ROWS via cp.async.16 (row-major tile, stride 516).
// y-class blocks stage img COLUMNS via cp.async.8 (column tile, stride 10) —
// this replaces the old g_imgT pre-transpose entirely.
// ---------------------------------------------------------------------------
__global__ __launch_bounds__(TB, 5) void dht_main(const float* __restrict__ img) {
    __shared__ __align__(16) float sbuf[2 * YBUF];   // 41 KB, union of layouts

    const int p   = blockIdx.x;
    const int sp  = blockIdx.y;
    const int tid = threadIdx.x;
    const int w   = tid >> 5;
    const int ln  = tid & 31;

    // ---- pair-slot -> (t0, t1) mapping (same f32 class within each pair) --
    int t0, t1;
    if      (p <  44) { t0 = 46 + 2 * p;        t1 = t0 + 1; }   // X: 46..133
    else if (p == 44) { t0 = 134;               t1 = -1;     }   // X solo
    else if (p == 45) { t0 = 45;                t1 = -1;     }   // boundary solo
    else if (p <  68) { int j = p - 46; t0 = 2 * j;       t1 = t0 + 1; } // Y: 0..43
    else if (p == 68) { t0 = 44;                t1 = -1;     }   // Y solo
    else if (p <  91) { int j = p - 69; t0 = 136 + 2 * j; t1 = t0 + 1; } // Y: 136..179
    else              { t0 = 135;               t1 = -1;     }   // boundary solo
    const bool dual = (t1 >= 0);
    const int  tb   = dual ? t1 : t0;

    // ---- per-theta constants (identical arithmetic to reference) ----------
    const float thetaA = __fmul_rn((float)t0, 0.017453292519943295f);
    const float cA = cosf(thetaA), sA = sinf(thetaA);
    const bool use_x = fabsf(sA) >= fabsf(cA);
    const float denA  = use_x ? sA : cA;
    const float coefA = use_x ? cA : sA;
    const float rdenA = __fdiv_rn(1.0f, denA);
    const float ndenA = -denA;
    const float ncoefA = -coefA;

    const float thetaB = __fmul_rn((float)tb, 0.017453292519943295f);
    const float cB = cosf(thetaB), sB = sinf(thetaB);
    const bool use_xB = fabsf(sB) >= fabsf(cB);  // == use_x within every pair
    const float denB  = use_xB ? sB : cB;
    const float coefB = use_xB ? cB : sB;
    const float rdenB = __fdiv_rn(1.0f, denB);
    const float ndenB = -denB;
    const float ncoefB = -coefB;

    // rho table: f32 linspace(-diag, diag, 725) (theta-independent).
    const float diag  = __fsqrt_rn(524288.0f);
    const float delta = __fdiv_rn(__fadd_rn(diag, diag), 724.0f);
    const float ndiag = -diag;

    const int r0 = 96 * w + ln, r1 = r0 + 32, r2 = r0 + 64;
    const float rho0 = (r0 == NUM_R - 1) ? diag : __fadd_rn(ndiag, __fmul_rn((float)r0, delta));
    const float rho1 = (r1 == NUM_R - 1) ? diag : __fadd_rn(ndiag, __fmul_rn((float)r1, delta));
    const float rho2 = (r2 == NUM_R - 1) ? diag : __fadd_rn(ndiag, __fmul_rn((float)r2, delta));

    const ull rho01   = pk2(rho0, rho1);
    const ull rden2A  = pk2(rdenA, rdenA);
    const ull nden2A  = pk2(ndenA, ndenA);
    const ull ncoef2A = pk2(ncoefA, ncoefA);
    const ull rden2B  = pk2(rdenB, rdenB);
    const ull nden2B  = pk2(ndenB, ndenB);
    const ull ncoef2B = pk2(ncoefB, ncoefB);

    // Warp-uniform rho bounds for the band test (+/- delta slack).
    const float rhoA = ndiag + ((float)(96 * w) - 1.0f) * delta;
    const float rhoB = ndiag + ((float)(96 * w + 95) + 1.0f) * delta;

    const int nbase0 = sp * NROWS;

    float a0A = 0.0f, a1A = 0.0f, a2A = 0.0f;
    float a0B = 0.0f, a1B = 0.0f, a2B = 0.0f;

    // ---- zero the pad slots (cp.async never touches them) -----------------
    if (use_x) {
        if (tid < 2 * CHUNK) {
            int b = tid >> 3, j = tid & 7;
            *(float4*)(&sbuf[b * XBUF + j * XSTRIDE + IMG_N]) =
                make_float4(0.f, 0.f, 0.f, 0.f);
        }
    } else {
        if (tid < 2 * YSTRIDE) {
            int b = tid / YSTRIDE, k = tid % YSTRIDE;
            sbuf[b * YBUF + IMG_N * YSTRIDE + k] = 0.0f;   // x=512 pad row
        }
    }

    // ---- staging routines --------------------------------------------------
    // x-class: chunk rows of img -> row-major tile (1024 f4, 4/thread, cg.16)
    // y-class: img columns nb..nb+7 -> column tile   (2048 8B, 8/thread, ca.8)
    const float4* __restrict__ gxbase =
        (const float4*)(img + (size_t)nbase0 * IMG_N);

    if (use_x) {
#pragma unroll
        for (int l = 0; l < 4; l++) {
            int idx = tid + l * TB;
            int jr = idx >> 7, cx = idx & 127;
            cpasync16(&sbuf[jr * XSTRIDE + cx * 4], &gxbase[idx]);
        }
    } else {
        const int nb = nbase0;                 // chunk 0 column base
#pragma unroll
        for (int l = 0; l < 8; l++) {
            int idx = tid + l * TB;            // 0..2047
            int x = idx >> 2, h = idx & 3;
            cpasync8(&sbuf[x * YSTRIDE + 2 * h],
                     &img[(size_t)x * IMG_N + nb + 2 * h]);
        }
    }
    cpasync_commit();

    for (int cb = 0; cb < NCHUNK; cb++) {
        const int bufsel = (cb + 1) & 1;
        if (cb + 1 < NCHUNK) {                 // prefetch next chunk
            if (use_x) {
                const float4* g = gxbase + (size_t)(cb + 1) * CHUNK * (IMG_N / 4);
                float* bnext = sbuf + bufsel * XBUF;
#pragma unroll
                for (int l = 0; l < 4; l++) {
                    int idx = tid + l * TB;
                    int jr = idx >> 7, cx = idx & 127;
                    cpasync16(&bnext[jr * XSTRIDE + cx * 4], &g[idx]);
                }
            } else {
                const int nb = nbase0 + (cb + 1) * CHUNK;
                float* bnext = sbuf + bufsel * YBUF;
#pragma unroll
                for (int l = 0; l < 8; l++) {
                    int idx = tid + l * TB;
                    int x = idx >> 2, h = idx & 3;
                    cpasync8(&bnext[x * YSTRIDE + 2 * h],
                             &img[(size_t)x * IMG_N + nb + 2 * h]);
                }
            }
            cpasync_commit();
            cpasync_wait<1>();                 // chunk cb complete
        } else {
            cpasync_wait<0>();
        }
        __syncthreads();                       // data visible to all warps

        // ---- union band test over both thetas (8 corners) -----------------
        const float n0f = (float)(nbase0 + cb * CHUNK);
        const float n1f = n0f + (float)(CHUNK - 1);
        float yA00 = (rhoA - n0f * coefA) * rdenA;
        float yA01 = (rhoA - n1f * coefA) * rdenA;
        float yA10 = (rhoB - n0f * coefA) * rdenA;
        float yA11 = (rhoB - n1f * coefA) * rdenA;
        float yB00 = (rhoA - n0f * coefB) * rdenB;
        float yB01 = (rhoA - n1f * coefB) * rdenB;
        float yB10 = (rhoB - n0f * coefB) * rdenB;
        float yB11 = (rhoB - n1f * coefB) * rdenB;
        float mx = fmaxf(fmaxf(fmaxf(yA00, yA01), fmaxf(yA10, yA11)),
                         fmaxf(fmaxf(yB00, yB01), fmaxf(yB10, yB11)));
        float mn = fminf(fminf(fminf(yA00, yA01), fminf(yA10, yA11)),
                         fminf(fminf(yB00, yB01), fminf(yB10, yB11)));
        bool live = (mx >= -4.0f) && (mn <= (float)IMG_N + 4.0f);

        if (live) {
            if (use_x) {
                const float* bcur = sbuf + (cb & 1) * XBUF;
                chunk_body<XSTRIDE, 1>(bcur, n0f, rho01, rho2,
                    ncoef2A, rden2A, nden2A, rdenA, ndenA,
                    ncoef2B, rden2B, nden2B, rdenB, ndenB,
                    a0A, a1A, a2A, a0B, a1B, a2B);
            } else {
                const float* bcur = sbuf + (cb & 1) * YBUF;
                chunk_body<1, YSTRIDE>(bcur, n0f, rho01, rho2,
                    ncoef2A, rden2A, nden2A, rdenA, ndenA,
                    ncoef2B, rden2B, nden2B, rdenB, ndenB,
                    a0A, a1A, a2A, a0B, a1B, a2B);
            }
        }
        __syncthreads();                       // compute done before buffer reuse
    }

    // Partial-sum stores: scratch[sp][t][r] (32-wide coalesced segments).
    float* dst0 = g_scratch + ((size_t)sp * NUM_T + t0) * NUM_R;
    dst0[r0] = a0A;
    if (r1 < NUM_R) dst0[r1] = a1A;
    if (r2 < NUM_R) dst0[r2] = a2A;
    if (dual) {
        float* dst1 = g_scratch + ((size_t)sp * NUM_T + t1) * NUM_R;
        dst1[r0] = a0B;
        if (r1 < NUM_R) dst1[r1] = a1B;
        if (r2 < NUM_R) dst1[r2] = a2B;
    }
}

// ---------------------------------------------------------------------------
// Deterministic reduce over NSPLIT partials (fixed sp order); out[r*180 + t].
// ---------------------------------------------------------------------------
__global__ void dht_reduce(float* __restrict__ out) {
    int i = blockIdx.x * 256 + threadIdx.x;     // i = t*NUM_R + r
    if (i < NUM_T * NUM_R) {
        float v = g_scratch[i];
#pragma unroll
        for (int sp = 1; sp < NSPLIT; sp++)
            v = __fadd_rn(v, g_scratch[(size_t)sp * NUM_T * NUM_R + i]);
        int t = i / NUM_R;
        int r = i - t * NUM_R;
        out[r * NUM_T + t] = v;
    }
}

// ---------------------------------------------------------------------------
extern "C" void kernel_launch(void* const* d_in, const int* in_sizes, int n_in,
                              void* d_out, int out_size) {
    const float* img = (const float*)d_in[0];
    float* out = (float*)d_out;

    dht_main<<<dim3(NPAIR, NSPLIT), TB>>>(img);
    dht_reduce<<<(NUM_T * NUM_R + 255) / 256, 256>>>(out);
}

// round 16
// speedup vs baseline: 1.3805x; 1.3805x over previous
#include <cuda_runtime.h>

#define NUM_R 725
#define NUM_T 180
#define IMG_N 512
#define NSPLIT 8                 // n-dimension split (92x8=736 blocks ~ 1 wave @5/SM)
#define TB 256                   // threads per block
#define NROWS (IMG_N / NSPLIT)   // 64 sweep rows per block
#define CHUNK 8                  // rows per pipeline stage
#define ROWSTRIDE 516            // 512 data + 4 pad floats (16B-aligned)
#define NCHUNK (NROWS / CHUNK)   // 8 stages
#define NPAIR 92                 // theta pair-slots (88 pairs + 4 solos)

// Scratch (device globals per the allocation-free rule)
__device__ float g_imgT[IMG_N * IMG_N];                 // transposed image
__device__ float g_scratch[NSPLIT * NUM_T * NUM_R];     // partials [sp][t][r]

typedef unsigned long long ull;

// ---- packed f32x2 helpers (Blackwell) --------------------------------------
__device__ __forceinline__ ull pk2(float lo, float hi) {
    ull r; asm("mov.b64 %0, {%1, %2};" : "=l"(r) : "f"(lo), "f"(hi)); return r;
}
__device__ __forceinline__ void upk2(float& lo, float& hi, ull v) {
    asm("mov.b64 {%0, %1}, %2;" : "=f"(lo), "=f"(hi) : "l"(v));
}
__device__ __forceinline__ ull mul2(ull a, ull b) {
    ull d; asm("mul.rn.f32x2 %0, %1, %2;" : "=l"(d) : "l"(a), "l"(b)); return d;
}
__device__ __forceinline__ ull add2(ull a, ull b) {
    ull d; asm("add.rn.f32x2 %0, %1, %2;" : "=l"(d) : "l"(a), "l"(b)); return d;
}
__device__ __forceinline__ ull fma2(ull a, ull b, ull c) {
    ull d; asm("fma.rn.f32x2 %0, %1, %2, %3;" : "=l"(d) : "l"(a), "l"(b), "l"(c)); return d;
}

// ---- cp.async helpers ------------------------------------------------------
__device__ __forceinline__ void cpasync16(void* smem, const void* gmem) {
    unsigned sa = (unsigned)__cvta_generic_to_shared(smem);
    asm volatile("cp.async.cg.shared.global [%0], [%1], 16;" :: "r"(sa), "l"(gmem));
}
__device__ __forceinline__ void cpasync_commit() {
    asm volatile("cp.async.commit_group;");
}
template <int N>
__device__ __forceinline__ void cpasync_wait() {
    asm volatile("cp.async.wait_group %0;" :: "n"(N));
}

// ---------------------------------------------------------------------------
// Transpose (proven scalar 32x32 pattern, both phases conflict-free):
// g_imgT[a*512 + b] = img[b*512 + a]
// ---------------------------------------------------------------------------
__global__ void dht_transpose(const float* __restrict__ img) {
    __shared__ float tile[32][33];
    int bx = blockIdx.x * 32, by = blockIdx.y * 32;
    int tx = threadIdx.x, ty = threadIdx.y;
#pragma unroll
    for (int i = 0; i < 32; i += 8)
        tile[ty + i][tx] = img[(by + ty + i) * IMG_N + (bx + tx)];
    __syncthreads();
#pragma unroll
    for (int i = 0; i < 32; i += 8)
        g_imgT[(bx + ty + i) * IMG_N + (by + tx)] = tile[tx][ty + i];
}

// ---------------------------------------------------------------------------
// Main Hough kernel, theta-paired, incremental-y inner loop.
// blockIdx.x = pair slot, blockIdx.y = split. Two adjacent same-class thetas
// per block from one staged chunk stream. Warp w owns rhos [96w, 96w+96);
// lane l handles r = 96w + 32k + l (k=0..2). Union 8-corner band test per
// chunk skips dead tiles. Zero-padded smem rows: OOB -> min(u,512) -> 0.
// Inner loop: exact RN Markstein division ONCE per chunk (j=0), then
// y(n+1) = y(n) + RN(-coef/den) packed adds (drift << rounding threshold).
// ---------------------------------------------------------------------------
__global__ __launch_bounds__(TB, 5) void dht_main(const float* __restrict__ img) {
    __shared__ float buf[2][CHUNK * ROWSTRIDE];   // 33 KB

    const int p   = blockIdx.x;
    const int sp  = blockIdx.y;
    const int tid = threadIdx.x;
    const int w   = tid >> 5;
    const int ln  = tid & 31;

    // ---- pair-slot -> (t0, t1) mapping (same f32 class within each pair) --
    int t0, t1;
    if      (p <  44) { t0 = 46 + 2 * p;        t1 = t0 + 1; }   // X: 46..133
    else if (p == 44) { t0 = 134;               t1 = -1;     }   // X solo
    else if (p == 45) { t0 = 45;                t1 = -1;     }   // boundary solo
    else if (p <  68) { int j = p - 46; t0 = 2 * j;       t1 = t0 + 1; } // Y: 0..43
    else if (p == 68) { t0 = 44;                t1 = -1;     }   // Y solo
    else if (p <  91) { int j = p - 69; t0 = 136 + 2 * j; t1 = t0 + 1; } // Y: 136..179
    else              { t0 = 135;               t1 = -1;     }   // boundary solo
    const bool dual = (t1 >= 0);
    const int  tb   = dual ? t1 : t0;

    // ---- per-theta constants (identical arithmetic to reference) ----------
    const float thetaA = __fmul_rn((float)t0, 0.017453292519943295f);
    const float cA = cosf(thetaA), sA = sinf(thetaA);
    const bool use_x = fabsf(sA) >= fabsf(cA);
    const float denA  = use_x ? sA : cA;
    const float coefA = use_x ? cA : sA;
    const float rdenA = __fdiv_rn(1.0f, denA);
    const float ndenA = -denA;
    const float ncoefA = -coefA;

    const float thetaB = __fmul_rn((float)tb, 0.017453292519943295f);
    const float cB = cosf(thetaB), sB = sinf(thetaB);
    const bool use_xB = fabsf(sB) >= fabsf(cB);  // == use_x within every pair
    const float denB  = use_xB ? sB : cB;
    const float coefB = use_xB ? cB : sB;
    const float rdenB = __fdiv_rn(1.0f, denB);
    const float ndenB = -denB;
    const float ncoefB = -coefB;

    const float* __restrict__ src = use_x ? img : g_imgT;

    // Per-n step of y: delta = RN((-coef) * rden); packed copies for the pair.
    const float dltA = __fmul_rn(ncoefA, rdenA);
    const float dltB = __fmul_rn(ncoefB, rdenB);
    const ull  dltA2 = pk2(dltA, dltA);
    const ull  dltB2 = pk2(dltB, dltB);

    // rho table: f32 linspace(-diag, diag, 725) (theta-independent).
    const float diag  = __fsqrt_rn(524288.0f);
    const float delta = __fdiv_rn(__fadd_rn(diag, diag), 724.0f);
    const float ndiag = -diag;

    const int r0 = 96 * w + ln, r1 = r0 + 32, r2 = r0 + 64;
    const float rho0 = (r0 == NUM_R - 1) ? diag : __fadd_rn(ndiag, __fmul_rn((float)r0, delta));
    const float rho1 = (r1 == NUM_R - 1) ? diag : __fadd_rn(ndiag, __fmul_rn((float)r1, delta));
    const float rho2 = (r2 == NUM_R - 1) ? diag : __fadd_rn(ndiag, __fmul_rn((float)r2, delta));

    const ull rho01   = pk2(rho0, rho1);
    const ull rden2A  = pk2(rdenA, rdenA);
    const ull nden2A  = pk2(ndenA, ndenA);
    const ull ncoef2A = pk2(ncoefA, ncoefA);
    const ull rden2B  = pk2(rdenB, rdenB);
    const ull nden2B  = pk2(ndenB, ndenB);
    const ull ncoef2B = pk2(ncoefB, ncoefB);

    // Warp-uniform rho bounds for the band test (+/- delta slack).
    const float rhoA = ndiag + ((float)(96 * w) - 1.0f) * delta;
    const float rhoB = ndiag + ((float)(96 * w + 95) + 1.0f) * delta;

    const int nbase0 = sp * NROWS;

    float a0A = 0.0f, a1A = 0.0f, a2A = 0.0f;
    float a0B = 0.0f, a1B = 0.0f, a2B = 0.0f;

    // Zero the pad slots of both buffers once (cp.async never touches them).
    if (tid < 2 * CHUNK) {
        int b = tid >> 3, j = tid & 7;
        *(float4*)(&buf[b][j * ROWSTRIDE + IMG_N]) = make_float4(0.f, 0.f, 0.f, 0.f);
    }

    const float4* __restrict__ gbase = (const float4*)(src + (size_t)nbase0 * IMG_N);

    // Prologue: prefetch chunk 0 into buffer 0.
    {
#pragma unroll
        for (int l = 0; l < 4; l++) {
            int idx = tid + l * TB;            // 0..1023
            int jr = idx >> 7, cx = idx & 127;
            cpasync16(&((float4*)(&buf[0][jr * ROWSTRIDE]))[cx], &gbase[idx]);
        }
        cpasync_commit();
    }

    for (int cb = 0; cb < NCHUNK; cb++) {
        if (cb + 1 < NCHUNK) {                 // prefetch next chunk
            const float4* g = gbase + (size_t)(cb + 1) * CHUNK * (IMG_N / 4);
            float* bnext = buf[(cb + 1) & 1];
#pragma unroll
            for (int l = 0; l < 4; l++) {
                int idx = tid + l * TB;
                int jr = idx >> 7, cx = idx & 127;
                cpasync16(&((float4*)(bnext + jr * ROWSTRIDE))[cx], &g[idx]);
            }
            cpasync_commit();
            cpasync_wait<1>();                 // chunk cb complete
        } else {
            cpasync_wait<0>();
        }
        __syncthreads();                       // data visible to all warps

        // ---- union band test over both thetas (8 corners) -----------------
        const float n0f = (float)(nbase0 + cb * CHUNK);
        const float n1f = n0f + (float)(CHUNK - 1);
        float yA00 = (rhoA - n0f * coefA) * rdenA;
        float yA01 = (rhoA - n1f * coefA) * rdenA;
        float yA10 = (rhoB - n0f * coefA) * rdenA;
        float yA11 = (rhoB - n1f * coefA) * rdenA;
        float yB00 = (rhoA - n0f * coefB) * rdenB;
        float yB01 = (rhoA - n1f * coefB) * rdenB;
        float yB10 = (rhoB - n0f * coefB) * rdenB;
        float yB11 = (rhoB - n1f * coefB) * rdenB;
        float mx = fmaxf(fmaxf(fmaxf(yA00, yA01), fmaxf(yA10, yA11)),
                         fmaxf(fmaxf(yB00, yB01), fmaxf(yB10, yB11)));
        float mn = fminf(fminf(fminf(yA00, yA01), fminf(yA10, yA11)),
                         fminf(fminf(yB00, yB01), fminf(yB10, yB11)));
        bool live = (mx >= -4.0f) && (mn <= (float)IMG_N + 4.0f);

        if (live) {
            const float* __restrict__ bcur = buf[cb & 1];
            const ull nf02 = pk2(n0f, n0f);

            // ---- exact RN Markstein reseed at n = n0 (per chunk) ----------
            ull nncA = mul2(nf02, ncoef2A);
            ull numA = add2(rho01, nncA);
            ull qA   = mul2(numA, rden2A);
            qA = fma2(fma2(nden2A, qA, numA), rden2A, qA);   // RN(num/den)
            float nnlA, nnhA; upk2(nnlA, nnhA, nncA);
            float numsA = __fadd_rn(rho2, nnlA);
            float q0sA  = __fmul_rn(numsA, rdenA);
            float qsA   = __fmaf_rn(__fmaf_rn(ndenA, q0sA, numsA), rdenA, q0sA);

            ull nncB = mul2(nf02, ncoef2B);
            ull numB = add2(rho01, nncB);
            ull qB   = mul2(numB, rden2B);
            qB = fma2(fma2(nden2B, qB, numB), rden2B, qB);
            float nnlB, nnhB; upk2(nnlB, nnhB, nncB);
            float numsB = __fadd_rn(rho2, nnlB);
            float q0sB  = __fmul_rn(numsB, rdenB);
            float qsB   = __fmaf_rn(__fmaf_rn(ndenB, q0sB, numsB), rdenB, q0sB);

#pragma unroll
            for (int j = 0; j < CHUNK; j++) {
                const float* __restrict__ row = bcur + j * ROWSTRIDE;

                float qaA, qbA; upk2(qaA, qbA, qA);
                float qaB, qbB; upk2(qaB, qbB, qB);

                unsigned u0A = min((unsigned)__float2int_rn(qaA), (unsigned)IMG_N);
                unsigned u1A = min((unsigned)__float2int_rn(qbA), (unsigned)IMG_N);
                unsigned u2A = min((unsigned)__float2int_rn(qsA), (unsigned)IMG_N);
                unsigned u0B = min((unsigned)__float2int_rn(qaB), (unsigned)IMG_N);
                unsigned u1B = min((unsigned)__float2int_rn(qbB), (unsigned)IMG_N);
                unsigned u2B = min((unsigned)__float2int_rn(qsB), (unsigned)IMG_N);
                a0A = __fadd_rn(a0A, row[u0A]);
                a1A = __fadd_rn(a1A, row[u1A]);
                a2A = __fadd_rn(a2A, row[u2A]);
                a0B = __fadd_rn(a0B, row[u0B]);
                a1B = __fadd_rn(a1B, row[u1B]);
                a2B = __fadd_rn(a2B, row[u2B]);

                // incremental y: one packed add + one scalar add per theta
                qA  = add2(qA, dltA2);
                qsA = __fadd_rn(qsA, dltA);
                qB  = add2(qB, dltB2);
                qsB = __fadd_rn(qsB, dltB);
            }
        }
        __syncthreads();                       // compute done before buffer reuse
    }

    // Partial-sum stores: scratch[sp][t][r] (32-wide coalesced segments).
    float* dst0 = g_scratch + ((size_t)sp * NUM_T + t0) * NUM_R;
    dst0[r0] = a0A;
    if (r1 < NUM_R) dst0[r1] = a1A;
    if (r2 < NUM_R) dst0[r2] = a2A;
    if (dual) {
        float* dst1 = g_scratch + ((size_t)sp * NUM_T + t1) * NUM_R;
        dst1[r0] = a0B;
        if (r1 < NUM_R) dst1[r1] = a1B;
        if (r2 < NUM_R) dst1[r2] = a2B;
    }
}

// ---------------------------------------------------------------------------
// Deterministic reduce over NSPLIT partials (fixed sp order); out[r*180 + t].
// ---------------------------------------------------------------------------
__global__ void dht_reduce(float* __restrict__ out) {
    int i = blockIdx.x * 256 + threadIdx.x;     // i = t*NUM_R + r
    if (i < NUM_T * NUM_R) {
        float v = g_scratch[i];
#pragma unroll
        for (int sp = 1; sp < NSPLIT; sp++)
            v = __fadd_rn(v, g_scratch[(size_t)sp * NUM_T * NUM_R + i]);
        int t = i / NUM_R;
        int r = i - t * NUM_R;
        out[r * NUM_T + t] = v;
    }
}

// ---------------------------------------------------------------------------
extern "C" void kernel_launch(void* const* d_in, const int* in_sizes, int n_in,
                              void* d_out, int out_size) {
    const float* img = (const float*)d_in[0];
    float* out = (float*)d_out;

    dht_transpose<<<dim3(IMG_N / 32, IMG_N / 32), dim3(32, 8)>>>(img);
    dht_main<<<dim3(NPAIR, NSPLIT), TB>>>(img);
    dht_reduce<<<(NUM_T * NUM_R + 255) / 256, 256>>>(out);
}